// round 2
// baseline (speedup 1.0000x reference)
#include <cuda_runtime.h>

#define HW     512
#define NB     16
#define PLANE  (HW * HW)          // 262144
#define NPIX   (NB * PLANE)       // 4194304
#define GROUPS (NPIX / 4)         // 1048576 pixel-quads

// Scratch planes (reused):
//   g_A : S1 (sum over channels of x), later sigma
//   g_B : S2 (sum over channels of x^2), later t = sum_c v^2
//   g_M : local mean m
__device__ float g_A[NPIX];
__device__ float g_Bp[NPIX];
__device__ float g_M[NPIX];
__device__ float g_filt[9 * 12];      // rows padded to 12 floats for float4 loads
__device__ float g_part[NB * 256];    // per-block sigma partial sums
__device__ float g_sum[NB];           // per-batch mean(sigma)

// ---------------------------------------------------------------------------
// K0: normalize filter: f = (filt + 10) / sum(filt + 10), store rows padded
// ---------------------------------------------------------------------------
__global__ void k_filt(const float* __restrict__ filt) {
    __shared__ float red[4];
    int t = threadIdx.x;                       // 128 threads
    float v = (t < 81) ? (filt[t] + 10.0f) : 0.0f;
    float s = v;
    #pragma unroll
    for (int o = 16; o; o >>= 1) s += __shfl_xor_sync(0xffffffffu, s, o);
    if ((t & 31) == 0) red[t >> 5] = s;
    __syncthreads();
    float total = red[0] + red[1] + red[2] + red[3];
    if (t < 108) g_filt[t] = 0.0f;             // zero padding lanes
    __syncthreads();
    if (t < 81) {
        int r = t / 9, c = t - r * 9;
        g_filt[r * 12 + c] = v / total;
    }
}

// ---------------------------------------------------------------------------
// K1: per-pixel channel sums S1, S2 (vectorized: 4 pixels = 3 float4 per thread)
// ---------------------------------------------------------------------------
__global__ void k_sums(const float* __restrict__ x) {
    int i = blockIdx.x * blockDim.x + threadIdx.x;     // pixel-quad index
    const float4* xp = (const float4*)x;
    float4 a = xp[i * 3 + 0];
    float4 b = xp[i * 3 + 1];
    float4 c = xp[i * 3 + 2];
    float4 s1, s2;
    s1.x = a.x + a.y + a.z;  s2.x = a.x * a.x + a.y * a.y + a.z * a.z;
    s1.y = a.w + b.x + b.y;  s2.y = a.w * a.w + b.x * b.x + b.y * b.y;
    s1.z = b.z + b.w + c.x;  s2.z = b.z * b.z + b.w * b.w + c.x * c.x;
    s1.w = c.y + c.z + c.w;  s2.w = c.y * c.y + c.z * c.z + c.w * c.w;
    ((float4*)g_A)[i]  = s1;
    ((float4*)g_Bp)[i] = s2;
}

// ---------------------------------------------------------------------------
// Tiled 9x9 conv core. Block = 256 threads -> 64x16 outputs, 4 horiz. px/thread.
// Tile: 24 rows x 72 cols (halo 4 each side), filter rows cached in smem.
// PHASE 0: conv(S1) -> m ; also t = S2 - 2 m S1 + 3 m^2 written over g_Bp
// PHASE 1: conv(t)  -> sigma (over g_A) + per-block sigma sums
// ---------------------------------------------------------------------------
template <int PHASE>
__global__ void k_conv() {
    __shared__ float tile[24 * 72];
    __shared__ float fsh[9 * 12];
    __shared__ float wsum[8];

    const int b  = blockIdx.z;
    const int bx = blockIdx.x;     // 0..7   (64-wide tiles)
    const int by = blockIdx.y;     // 0..31  (16-high tiles)
    const int x0 = bx * 64 - 4;
    const int y0 = by * 16 - 4;

    const float* __restrict__ src = (PHASE == 0) ? g_A : g_Bp;

    for (int i = threadIdx.x; i < 24 * 72; i += 256) {
        int row = i / 72, col = i - row * 72;
        int gx = x0 + col, gy = y0 + row;
        float v = 0.0f;
        if ((unsigned)gx < (unsigned)HW && (unsigned)gy < (unsigned)HW)
            v = src[b * PLANE + gy * HW + gx];
        tile[i] = v;
    }
    if (threadIdx.x < 108) fsh[threadIdx.x] = g_filt[threadIdx.x];
    __syncthreads();

    const int tx = threadIdx.x & 15;     // 0..15 -> x quad
    const int ty = threadIdx.x >> 4;     // 0..15 -> y row

    float acc0 = 0.f, acc1 = 0.f, acc2 = 0.f, acc3 = 0.f;
    #pragma unroll
    for (int r = 0; r < 9; ++r) {
        const float* rp = &tile[(ty + r) * 72 + tx * 4];
        float4 v0 = *(const float4*)(rp + 0);
        float4 v1 = *(const float4*)(rp + 4);
        float4 v2 = *(const float4*)(rp + 8);
        float w[12] = {v0.x, v0.y, v0.z, v0.w, v1.x, v1.y, v1.z, v1.w,
                       v2.x, v2.y, v2.z, v2.w};
        const float* fp = &fsh[r * 12];
        float4 f0 = *(const float4*)(fp + 0);
        float4 f1 = *(const float4*)(fp + 4);
        float fr[9] = {f0.x, f0.y, f0.z, f0.w, f1.x, f1.y, f1.z, f1.w, fp[8]};
        #pragma unroll
        for (int c = 0; c < 9; ++c) {
            acc0 = fmaf(fr[c], w[c + 0], acc0);
            acc1 = fmaf(fr[c], w[c + 1], acc1);
            acc2 = fmaf(fr[c], w[c + 2], acc2);
            acc3 = fmaf(fr[c], w[c + 3], acc3);
        }
    }

    const int ox = bx * 64 + tx * 4;
    const int oy = by * 16 + ty;
    const int q  = (b * PLANE + oy * HW + ox) >> 2;    // float4 index

    if (PHASE == 0) {
        float4 m = make_float4(acc0, acc1, acc2, acc3);
        ((float4*)g_M)[q] = m;
        const float* cp = &tile[(ty + 4) * 72 + tx * 4 + 4];
        float4 s1 = *(const float4*)cp;
        float4 s2 = ((const float4*)g_Bp)[q];
        float4 t;
        t.x = s2.x - 2.0f * m.x * s1.x + 3.0f * m.x * m.x;
        t.y = s2.y - 2.0f * m.y * s1.y + 3.0f * m.y * m.y;
        t.z = s2.z - 2.0f * m.z * s1.z + 3.0f * m.z * m.z;
        t.w = s2.w - 2.0f * m.w * s1.w + 3.0f * m.w * m.w;
        ((float4*)g_Bp)[q] = t;
    } else {
        float4 sg;
        sg.x = sqrtf(fmaxf(acc0, 0.0f));
        sg.y = sqrtf(fmaxf(acc1, 0.0f));
        sg.z = sqrtf(fmaxf(acc2, 0.0f));
        sg.w = sqrtf(fmaxf(acc3, 0.0f));
        ((float4*)g_A)[q] = sg;
        float local = sg.x + sg.y + sg.z + sg.w;
        #pragma unroll
        for (int o = 16; o; o >>= 1) local += __shfl_xor_sync(0xffffffffu, local, o);
        if ((threadIdx.x & 31) == 0) wsum[threadIdx.x >> 5] = local;
        __syncthreads();
        if (threadIdx.x == 0) {
            float s = 0.0f;
            #pragma unroll
            for (int k = 0; k < 8; ++k) s += wsum[k];
            g_part[b * 256 + by * 8 + bx] = s;    // 32*8 = 256 blocks per batch
        }
    }
}

// ---------------------------------------------------------------------------
// K3.5: deterministic reduce of 256 block partials per batch -> mean(sigma)
// ---------------------------------------------------------------------------
__global__ void k_mean() {
    __shared__ float ws[8];
    int b = blockIdx.x;
    float v = g_part[b * 256 + threadIdx.x];
    #pragma unroll
    for (int o = 16; o; o >>= 1) v += __shfl_xor_sync(0xffffffffu, v, o);
    if ((threadIdx.x & 31) == 0) ws[threadIdx.x >> 5] = v;
    __syncthreads();
    if (threadIdx.x == 0) {
        float s = 0.0f;
        #pragma unroll
        for (int k = 0; k < 8; ++k) s += ws[k];
        g_sum[b] = s * (1.0f / (float)PLANE);
    }
}

// ---------------------------------------------------------------------------
// K4: out = (x - m) / max(mean_b, sigma)
// ---------------------------------------------------------------------------
__global__ void k_final(const float* __restrict__ x, float* __restrict__ out) {
    int i = blockIdx.x * blockDim.x + threadIdx.x;   // pixel-quad index
    int b = i >> 16;                                  // 65536 quads per batch
    float mean = g_sum[b];

    float4 m  = ((const float4*)g_M)[i];
    float4 sg = ((const float4*)g_A)[i];
    float r0 = 1.0f / fmaxf(mean, sg.x);
    float r1 = 1.0f / fmaxf(mean, sg.y);
    float r2 = 1.0f / fmaxf(mean, sg.z);
    float r3 = 1.0f / fmaxf(mean, sg.w);

    const float4* xp = (const float4*)x;
    float4 a = xp[i * 3 + 0];
    float4 bb = xp[i * 3 + 1];
    float4 c = xp[i * 3 + 2];

    float4 o0, o1, o2;
    o0.x = (a.x  - m.x) * r0;  o0.y = (a.y  - m.x) * r0;  o0.z = (a.z  - m.x) * r0;
    o0.w = (a.w  - m.y) * r1;
    o1.x = (bb.x - m.y) * r1;  o1.y = (bb.y - m.y) * r1;
    o1.z = (bb.z - m.z) * r2;  o1.w = (bb.w - m.z) * r2;
    o2.x = (c.x  - m.z) * r2;
    o2.y = (c.y  - m.w) * r3;  o2.z = (c.z  - m.w) * r3;  o2.w = (c.w  - m.w) * r3;

    float4* op = (float4*)out;
    op[i * 3 + 0] = o0;
    op[i * 3 + 1] = o1;
    op[i * 3 + 2] = o2;
}

// ---------------------------------------------------------------------------
extern "C" void kernel_launch(void* const* d_in, const int* in_sizes, int n_in,
                              void* d_out, int out_size) {
    const float* x    = (const float*)d_in[0];
    const float* filt = (const float*)d_in[1];
    float* out        = (float*)d_out;

    k_filt<<<1, 128>>>(filt);
    k_sums<<<GROUPS / 256, 256>>>(x);
    dim3 cgrid(8, 32, NB);
    k_conv<0><<<cgrid, 256>>>();
    k_conv<1><<<cgrid, 256>>>();
    k_mean<<<NB, 256>>>();
    k_final<<<GROUPS / 256, 256>>>(x, out);
}

// round 3
// speedup vs baseline: 1.0408x; 1.0408x over previous
#include <cuda_runtime.h>

#define HW     512
#define NB     16
#define PLANE  (HW * HW)          // 262144
#define NPIX   (NB * PLANE)       // 4194304
#define GROUPS (NPIX / 4)         // 1048576 pixel-quads

// Scratch planes:
//   g_A : sigma (written by conv1)
//   g_Bp: t = sum_c v^2 (written by conv0, read by conv1)
//   g_M : local mean m
__device__ float  g_A[NPIX];
__device__ float  g_Bp[NPIX];
__device__ float  g_M[NPIX];
__device__ float2 g_fpack[90];        // 9 rows x 10 packed filter pairs
__device__ float  g_part[NB * 64];    // per-block sigma partial sums (8x8 blocks/batch)
__device__ float  g_sum[NB];          // per-batch mean(sigma)

// packed fp32x2 FMA: d += a * b (two independent lanes)
__device__ __forceinline__ void ffma2(float2 &d, const float2 a, const float2 b) {
    asm("fma.rn.f32x2 %0, %1, %2, %0;"
        : "+l"(reinterpret_cast<unsigned long long &>(d))
        : "l"(reinterpret_cast<const unsigned long long &>(a)),
          "l"(reinterpret_cast<const unsigned long long &>(b)));
}

// ---------------------------------------------------------------------------
// K0: normalize filter f = (filt+10)/sum, build packed-pair layout:
//  row t, slots 0..4 : (f[2k], f[2k+1])  with f[9]=0
//  slots 5..8        : (f[2k+1], f[2k+2])
//  slot 9            : (0, f[0])
// ---------------------------------------------------------------------------
__global__ void k_filt(const float* __restrict__ filt) {
    __shared__ float nf[81];
    __shared__ float red[4];
    int t = threadIdx.x;                       // 128 threads
    float v = (t < 81) ? (filt[t] + 10.0f) : 0.0f;
    float s = v;
    #pragma unroll
    for (int o = 16; o; o >>= 1) s += __shfl_xor_sync(0xffffffffu, s, o);
    if ((t & 31) == 0) red[t >> 5] = s;
    __syncthreads();
    float total = red[0] + red[1] + red[2] + red[3];
    if (t < 81) nf[t] = v / total;
    __syncthreads();
    if (t < 90) {
        int r = t / 10, k = t - r * 10;
        const float* f = &nf[r * 9];
        float2 o;
        if (k < 5)      o = make_float2(f[2 * k], (2 * k + 1 < 9) ? f[2 * k + 1] : 0.0f);
        else if (k < 9) { int j = k - 5; o = make_float2(f[2 * j + 1], f[2 * j + 2]); }
        else            o = make_float2(0.0f, f[0]);
        g_fpack[r * 10 + k] = o;
    }
}

// ---------------------------------------------------------------------------
// Conv core: 64x64 output tile per block, 256 threads, 4x4 outputs/thread.
// Smem tile 72 rows x 72 cols (stride 76). Filter-pair packing + FFMA2.
// PHASE 0: loads x (NHWC, C=3), builds S1 tile + center S2 tile.
//          conv(S1) -> m ; t = S2 - 2 m S1 + 3 m^2 -> g_Bp ; m -> g_M
// PHASE 1: loads t plane; conv(t) -> sigma -> g_A ; block partial sums.
// ---------------------------------------------------------------------------
template <int PHASE>
__global__ void __launch_bounds__(256) k_conv(const float* __restrict__ x) {
    __shared__ float  tile[72 * 76];
    __shared__ float  s2c[(PHASE == 0) ? 64 * 64 : 1];
    __shared__ float2 sfp[90];
    __shared__ float  wsum[8];

    const int b  = blockIdx.z;
    const int bx = blockIdx.x;     // 0..7
    const int by = blockIdx.y;     // 0..7
    const int x0 = bx * 64 - 4;
    const int y0 = by * 64 - 4;
    const int tid = threadIdx.x;

    if (tid < 90) sfp[tid] = g_fpack[tid];

    // ---- load tile: 72 rows x 18 quads ----
    if (PHASE == 0) {
        for (int i = tid; i < 72 * 18; i += 256) {
            int row = i / 18, q = i - row * 18;
            int gy = y0 + row, gx = x0 + q * 4;
            float4 a = make_float4(0.f,0.f,0.f,0.f), bb = a, c = a;
            if ((unsigned)gy < (unsigned)HW && (unsigned)gx < (unsigned)HW) {
                const float4* p = (const float4*)x +
                    (((size_t)b * PLANE + (size_t)gy * HW + gx) >> 2) * 3;
                a = p[0]; bb = p[1]; c = p[2];
            }
            float4 s1, s2;
            s1.x = a.x + a.y + a.z;   s2.x = a.x*a.x + a.y*a.y + a.z*a.z;
            s1.y = a.w + bb.x + bb.y; s2.y = a.w*a.w + bb.x*bb.x + bb.y*bb.y;
            s1.z = bb.z + bb.w + c.x; s2.z = bb.z*bb.z + bb.w*bb.w + c.x*c.x;
            s1.w = c.y + c.z + c.w;   s2.w = c.y*c.y + c.z*c.z + c.w*c.w;
            *(float4*)&tile[row * 76 + q * 4] = s1;
            if (row >= 4 && row < 68 && q >= 1 && q <= 16)
                *(float4*)&s2c[(row - 4) * 64 + (q - 1) * 4] = s2;
        }
    } else {
        for (int i = tid; i < 72 * 18; i += 256) {
            int row = i / 18, q = i - row * 18;
            int gy = y0 + row, gx = x0 + q * 4;
            float4 v = make_float4(0.f,0.f,0.f,0.f);
            if ((unsigned)gy < (unsigned)HW && (unsigned)gx < (unsigned)HW)
                v = *(const float4*)&g_Bp[(size_t)b * PLANE + (size_t)gy * HW + gx];
            *(float4*)&tile[row * 76 + q * 4] = v;
        }
    }
    __syncthreads();

    const int tx = tid & 15;       // x quad  -> outputs 4*tx .. 4*tx+3
    const int ty = tid >> 4;       // y quad  -> outputs 4*ty .. 4*ty+3
    const int rbase = ty * 4;

    float2 acc[4][4];
    #pragma unroll
    for (int i = 0; i < 4; ++i)
        #pragma unroll
        for (int j = 0; j < 4; ++j) acc[i][j] = make_float2(0.f, 0.f);

    float2 W[4][6];
    #pragma unroll
    for (int j = 0; j < 4; ++j) {
        const float* p = &tile[(rbase + j) * 76 + tx * 4];
        float4 a = *(const float4*)p, bb = *(const float4*)(p + 4), c = *(const float4*)(p + 8);
        W[j][0] = make_float2(a.x, a.y);  W[j][1] = make_float2(a.z, a.w);
        W[j][2] = make_float2(bb.x, bb.y); W[j][3] = make_float2(bb.z, bb.w);
        W[j][4] = make_float2(c.x, c.y);  W[j][5] = make_float2(c.z, c.w);
    }

    #pragma unroll
    for (int t = 0; t < 9; ++t) {
        const float2* fp = &sfp[t * 10];
        float2 fe0 = fp[0], fe1 = fp[1], fe2 = fp[2], fe3 = fp[3], fe4 = fp[4];
        float2 fo0 = fp[5], fo1 = fp[6], fo2 = fp[7], fo3 = fp[8], f0z = fp[9];
        #pragma unroll
        for (int oy = 0; oy < 4; ++oy) {
            float2* w = W[(t + oy) & 3];
            ffma2(acc[oy][0], fe0, w[0]); ffma2(acc[oy][0], fe1, w[1]);
            ffma2(acc[oy][0], fe2, w[2]); ffma2(acc[oy][0], fe3, w[3]);
            ffma2(acc[oy][0], fe4, w[4]);
            ffma2(acc[oy][2], fe0, w[1]); ffma2(acc[oy][2], fe1, w[2]);
            ffma2(acc[oy][2], fe2, w[3]); ffma2(acc[oy][2], fe3, w[4]);
            ffma2(acc[oy][2], fe4, w[5]);
            ffma2(acc[oy][1], f0z, w[0]); ffma2(acc[oy][1], fo0, w[1]);
            ffma2(acc[oy][1], fo1, w[2]); ffma2(acc[oy][1], fo2, w[3]);
            ffma2(acc[oy][1], fo3, w[4]);
            ffma2(acc[oy][3], f0z, w[1]); ffma2(acc[oy][3], fo0, w[2]);
            ffma2(acc[oy][3], fo1, w[3]); ffma2(acc[oy][3], fo2, w[4]);
            ffma2(acc[oy][3], fo3, w[5]);
        }
        if (t < 8) {
            const float* p = &tile[(rbase + t + 4) * 76 + tx * 4];
            float4 a = *(const float4*)p, bb = *(const float4*)(p + 4), c = *(const float4*)(p + 8);
            float2* w = W[t & 3];
            w[0] = make_float2(a.x, a.y);  w[1] = make_float2(a.z, a.w);
            w[2] = make_float2(bb.x, bb.y); w[3] = make_float2(bb.z, bb.w);
            w[4] = make_float2(c.x, c.y);  w[5] = make_float2(c.z, c.w);
        }
    }

    const int ox  = bx * 64 + tx * 4;

    if (PHASE == 0) {
        #pragma unroll
        for (int oy = 0; oy < 4; ++oy) {
            int oyg = by * 64 + rbase + oy;
            int q   = ((size_t)b * PLANE + (size_t)oyg * HW + ox) >> 2;
            float m0 = acc[oy][0].x + acc[oy][0].y;
            float m1 = acc[oy][1].x + acc[oy][1].y;
            float m2 = acc[oy][2].x + acc[oy][2].y;
            float m3 = acc[oy][3].x + acc[oy][3].y;
            ((float4*)g_M)[q] = make_float4(m0, m1, m2, m3);
            float4 s1 = *(const float4*)&tile[(rbase + oy + 4) * 76 + tx * 4 + 4];
            float4 s2 = *(const float4*)&s2c[(rbase + oy) * 64 + tx * 4];
            float4 tt;
            tt.x = s2.x - 2.0f * m0 * s1.x + 3.0f * m0 * m0;
            tt.y = s2.y - 2.0f * m1 * s1.y + 3.0f * m1 * m1;
            tt.z = s2.z - 2.0f * m2 * s1.z + 3.0f * m2 * m2;
            tt.w = s2.w - 2.0f * m3 * s1.w + 3.0f * m3 * m3;
            ((float4*)g_Bp)[q] = tt;
        }
    } else {
        float local = 0.0f;
        #pragma unroll
        for (int oy = 0; oy < 4; ++oy) {
            int oyg = by * 64 + rbase + oy;
            int q   = ((size_t)b * PLANE + (size_t)oyg * HW + ox) >> 2;
            float4 sg;
            sg.x = sqrtf(fmaxf(acc[oy][0].x + acc[oy][0].y, 0.0f));
            sg.y = sqrtf(fmaxf(acc[oy][1].x + acc[oy][1].y, 0.0f));
            sg.z = sqrtf(fmaxf(acc[oy][2].x + acc[oy][2].y, 0.0f));
            sg.w = sqrtf(fmaxf(acc[oy][3].x + acc[oy][3].y, 0.0f));
            ((float4*)g_A)[q] = sg;
            local += sg.x + sg.y + sg.z + sg.w;
        }
        #pragma unroll
        for (int o = 16; o; o >>= 1) local += __shfl_xor_sync(0xffffffffu, local, o);
        if ((tid & 31) == 0) wsum[tid >> 5] = local;
        __syncthreads();
        if (tid == 0) {
            float s = 0.0f;
            #pragma unroll
            for (int k = 0; k < 8; ++k) s += wsum[k];
            g_part[b * 64 + by * 8 + bx] = s;
        }
    }
}

// ---------------------------------------------------------------------------
// K3: deterministic reduce of 64 block partials per batch -> mean(sigma)
// ---------------------------------------------------------------------------
__global__ void k_mean() {
    __shared__ float ws[2];
    int b = blockIdx.x;
    float v = g_part[b * 64 + threadIdx.x];
    #pragma unroll
    for (int o = 16; o; o >>= 1) v += __shfl_xor_sync(0xffffffffu, v, o);
    if ((threadIdx.x & 31) == 0) ws[threadIdx.x >> 5] = v;
    __syncthreads();
    if (threadIdx.x == 0)
        g_sum[b] = (ws[0] + ws[1]) * (1.0f / (float)PLANE);
}

// ---------------------------------------------------------------------------
// K4: out = (x - m) / max(mean_b, sigma)
// ---------------------------------------------------------------------------
__global__ void k_final(const float* __restrict__ x, float* __restrict__ out) {
    int i = blockIdx.x * blockDim.x + threadIdx.x;   // pixel-quad index
    int b = i >> 16;                                  // 65536 quads per batch
    float mean = g_sum[b];

    float4 m  = ((const float4*)g_M)[i];
    float4 sg = ((const float4*)g_A)[i];
    float r0 = 1.0f / fmaxf(mean, sg.x);
    float r1 = 1.0f / fmaxf(mean, sg.y);
    float r2 = 1.0f / fmaxf(mean, sg.z);
    float r3 = 1.0f / fmaxf(mean, sg.w);

    const float4* xp = (const float4*)x;
    float4 a = xp[i * 3 + 0];
    float4 bb = xp[i * 3 + 1];
    float4 c = xp[i * 3 + 2];

    float4 o0, o1, o2;
    o0.x = (a.x  - m.x) * r0;  o0.y = (a.y  - m.x) * r0;  o0.z = (a.z  - m.x) * r0;
    o0.w = (a.w  - m.y) * r1;
    o1.x = (bb.x - m.y) * r1;  o1.y = (bb.y - m.y) * r1;
    o1.z = (bb.z - m.z) * r2;  o1.w = (bb.w - m.z) * r2;
    o2.x = (c.x  - m.z) * r2;
    o2.y = (c.y  - m.w) * r3;  o2.z = (c.z  - m.w) * r3;  o2.w = (c.w  - m.w) * r3;

    float4* op = (float4*)out;
    op[i * 3 + 0] = o0;
    op[i * 3 + 1] = o1;
    op[i * 3 + 2] = o2;
}

// ---------------------------------------------------------------------------
extern "C" void kernel_launch(void* const* d_in, const int* in_sizes, int n_in,
                              void* d_out, int out_size) {
    const float* x    = (const float*)d_in[0];
    const float* filt = (const float*)d_in[1];
    float* out        = (float*)d_out;

    k_filt<<<1, 128>>>(filt);
    dim3 cgrid(8, 8, NB);
    k_conv<0><<<cgrid, 256>>>(x);
    k_conv<1><<<cgrid, 256>>>(x);
    k_mean<<<NB, 64>>>();
    k_final<<<GROUPS / 256, 256>>>(x, out);
}

// round 4
// speedup vs baseline: 1.0473x; 1.0063x over previous
#include <cuda_runtime.h>

#define HW     512
#define NB     16
#define PLANE  (HW * HW)          // 262144
#define NPIX   (NB * PLANE)       // 4194304
#define GROUPS (NPIX / 4)         // 1048576 pixel-quads

// Scratch planes:
//   g_A : sigma (written by conv1)
//   g_Bp: t = sum_c v^2 (written by conv0, read by conv1)
//   g_M : local mean m
__device__ float  g_A[NPIX];
__device__ float  g_Bp[NPIX];
__device__ float  g_M[NPIX];
__device__ float2 g_fpack[90];        // 9 rows x 10 packed filter pairs
__device__ float  g_part[NB * 64];    // per-block sigma partial sums (8x8 blocks/batch)
__device__ float  g_sum[NB];          // per-batch mean(sigma)

// packed fp32x2 FMA: d += a * b (two independent lanes)
__device__ __forceinline__ void ffma2(float2 &d, const float2 a, const float2 b) {
    asm("fma.rn.f32x2 %0, %1, %2, %0;"
        : "+l"(reinterpret_cast<unsigned long long &>(d))
        : "l"(reinterpret_cast<const unsigned long long &>(a)),
          "l"(reinterpret_cast<const unsigned long long &>(b)));
}

// ---------------------------------------------------------------------------
// K0: normalize filter f = (filt+10)/sum, build packed-pair layout:
//  row t, slots 0..4 : (f[2k], f[2k+1])  with f[9]=0
//  slots 5..8        : (f[2k+1], f[2k+2])
//  slot 9            : (0, f[0])
// ---------------------------------------------------------------------------
__global__ void k_filt(const float* __restrict__ filt) {
    __shared__ float nf[81];
    __shared__ float red[4];
    int t = threadIdx.x;                       // 128 threads
    float v = (t < 81) ? (filt[t] + 10.0f) : 0.0f;
    float s = v;
    #pragma unroll
    for (int o = 16; o; o >>= 1) s += __shfl_xor_sync(0xffffffffu, s, o);
    if ((t & 31) == 0) red[t >> 5] = s;
    __syncthreads();
    float total = red[0] + red[1] + red[2] + red[3];
    if (t < 81) nf[t] = v / total;
    __syncthreads();
    if (t < 90) {
        int r = t / 10, k = t - r * 10;
        const float* f = &nf[r * 9];
        float2 o;
        if (k < 5)      o = make_float2(f[2 * k], (2 * k + 1 < 9) ? f[2 * k + 1] : 0.0f);
        else if (k < 9) { int j = k - 5; o = make_float2(f[2 * j + 1], f[2 * j + 2]); }
        else            o = make_float2(0.0f, f[0]);
        g_fpack[r * 10 + k] = o;
    }
}

// ---------------------------------------------------------------------------
// Conv core: 64x64 output tile per block, 256 threads, 4x4 outputs/thread.
// Smem tile 72 rows x 72 cols (stride 76). Filter-pair packing + FFMA2.
// PHASE 0: loads x (NHWC, C=3), builds S1 tile + center S2 tile.
//          conv(S1) -> m ; t = S2 - 2 m S1 + 3 m^2 -> g_Bp ; m -> g_M
// PHASE 1: loads t plane; conv(t) -> sigma -> g_A ; block partial sums.
// ---------------------------------------------------------------------------
template <int PHASE>
__global__ void __launch_bounds__(256) k_conv(const float* __restrict__ x) {
    __shared__ float  tile[72 * 76];
    __shared__ float  s2c[(PHASE == 0) ? 64 * 64 : 1];
    __shared__ float2 sfp[90];
    __shared__ float  wsum[8];

    const int b  = blockIdx.z;
    const int bx = blockIdx.x;     // 0..7
    const int by = blockIdx.y;     // 0..7
    const int x0 = bx * 64 - 4;
    const int y0 = by * 64 - 4;
    const int tid = threadIdx.x;

    if (tid < 90) sfp[tid] = g_fpack[tid];

    // ---- load tile: 72 rows x 18 quads ----
    if (PHASE == 0) {
        for (int i = tid; i < 72 * 18; i += 256) {
            int row = i / 18, q = i - row * 18;
            int gy = y0 + row, gx = x0 + q * 4;
            float4 a = make_float4(0.f,0.f,0.f,0.f), bb = a, c = a;
            if ((unsigned)gy < (unsigned)HW && (unsigned)gx < (unsigned)HW) {
                const float4* p = (const float4*)x +
                    (((size_t)b * PLANE + (size_t)gy * HW + gx) >> 2) * 3;
                a = p[0]; bb = p[1]; c = p[2];
            }
            float4 s1, s2;
            s1.x = a.x + a.y + a.z;   s2.x = a.x*a.x + a.y*a.y + a.z*a.z;
            s1.y = a.w + bb.x + bb.y; s2.y = a.w*a.w + bb.x*bb.x + bb.y*bb.y;
            s1.z = bb.z + bb.w + c.x; s2.z = bb.z*bb.z + bb.w*bb.w + c.x*c.x;
            s1.w = c.y + c.z + c.w;   s2.w = c.y*c.y + c.z*c.z + c.w*c.w;
            *(float4*)&tile[row * 76 + q * 4] = s1;
            if (row >= 4 && row < 68 && q >= 1 && q <= 16)
                *(float4*)&s2c[(row - 4) * 64 + (q - 1) * 4] = s2;
        }
    } else {
        for (int i = tid; i < 72 * 18; i += 256) {
            int row = i / 18, q = i - row * 18;
            int gy = y0 + row, gx = x0 + q * 4;
            float4 v = make_float4(0.f,0.f,0.f,0.f);
            if ((unsigned)gy < (unsigned)HW && (unsigned)gx < (unsigned)HW)
                v = *(const float4*)&g_Bp[(size_t)b * PLANE + (size_t)gy * HW + gx];
            *(float4*)&tile[row * 76 + q * 4] = v;
        }
    }
    __syncthreads();

    const int tx = tid & 15;       // x quad  -> outputs 4*tx .. 4*tx+3
    const int ty = tid >> 4;       // y quad  -> outputs 4*ty .. 4*ty+3
    const int rbase = ty * 4;

    float2 acc[4][4];
    #pragma unroll
    for (int i = 0; i < 4; ++i)
        #pragma unroll
        for (int j = 0; j < 4; ++j) acc[i][j] = make_float2(0.f, 0.f);

    float2 W[4][6];
    #pragma unroll
    for (int j = 0; j < 4; ++j) {
        const float* p = &tile[(rbase + j) * 76 + tx * 4];
        float4 a = *(const float4*)p, bb = *(const float4*)(p + 4), c = *(const float4*)(p + 8);
        W[j][0] = make_float2(a.x, a.y);  W[j][1] = make_float2(a.z, a.w);
        W[j][2] = make_float2(bb.x, bb.y); W[j][3] = make_float2(bb.z, bb.w);
        W[j][4] = make_float2(c.x, c.y);  W[j][5] = make_float2(c.z, c.w);
    }

    #pragma unroll
    for (int t = 0; t < 9; ++t) {
        const float2* fp = &sfp[t * 10];
        float2 fe0 = fp[0], fe1 = fp[1], fe2 = fp[2], fe3 = fp[3], fe4 = fp[4];
        float2 fo0 = fp[5], fo1 = fp[6], fo2 = fp[7], fo3 = fp[8], f0z = fp[9];
        #pragma unroll
        for (int oy = 0; oy < 4; ++oy) {
            float2* w = W[(t + oy) & 3];
            ffma2(acc[oy][0], fe0, w[0]); ffma2(acc[oy][0], fe1, w[1]);
            ffma2(acc[oy][0], fe2, w[2]); ffma2(acc[oy][0], fe3, w[3]);
            ffma2(acc[oy][0], fe4, w[4]);
            ffma2(acc[oy][2], fe0, w[1]); ffma2(acc[oy][2], fe1, w[2]);
            ffma2(acc[oy][2], fe2, w[3]); ffma2(acc[oy][2], fe3, w[4]);
            ffma2(acc[oy][2], fe4, w[5]);
            ffma2(acc[oy][1], f0z, w[0]); ffma2(acc[oy][1], fo0, w[1]);
            ffma2(acc[oy][1], fo1, w[2]); ffma2(acc[oy][1], fo2, w[3]);
            ffma2(acc[oy][1], fo3, w[4]);
            ffma2(acc[oy][3], f0z, w[1]); ffma2(acc[oy][3], fo0, w[2]);
            ffma2(acc[oy][3], fo1, w[3]); ffma2(acc[oy][3], fo2, w[4]);
            ffma2(acc[oy][3], fo3, w[5]);
        }
        if (t < 8) {
            const float* p = &tile[(rbase + t + 4) * 76 + tx * 4];
            float4 a = *(const float4*)p, bb = *(const float4*)(p + 4), c = *(const float4*)(p + 8);
            float2* w = W[t & 3];
            w[0] = make_float2(a.x, a.y);  w[1] = make_float2(a.z, a.w);
            w[2] = make_float2(bb.x, bb.y); w[3] = make_float2(bb.z, bb.w);
            w[4] = make_float2(c.x, c.y);  w[5] = make_float2(c.z, c.w);
        }
    }

    const int ox  = bx * 64 + tx * 4;

    if (PHASE == 0) {
        #pragma unroll
        for (int oy = 0; oy < 4; ++oy) {
            int oyg = by * 64 + rbase + oy;
            int q   = ((size_t)b * PLANE + (size_t)oyg * HW + ox) >> 2;
            float m0 = acc[oy][0].x + acc[oy][0].y;
            float m1 = acc[oy][1].x + acc[oy][1].y;
            float m2 = acc[oy][2].x + acc[oy][2].y;
            float m3 = acc[oy][3].x + acc[oy][3].y;
            ((float4*)g_M)[q] = make_float4(m0, m1, m2, m3);
            float4 s1 = *(const float4*)&tile[(rbase + oy + 4) * 76 + tx * 4 + 4];
            float4 s2 = *(const float4*)&s2c[(rbase + oy) * 64 + tx * 4];
            float4 tt;
            tt.x = s2.x - 2.0f * m0 * s1.x + 3.0f * m0 * m0;
            tt.y = s2.y - 2.0f * m1 * s1.y + 3.0f * m1 * m1;
            tt.z = s2.z - 2.0f * m2 * s1.z + 3.0f * m2 * m2;
            tt.w = s2.w - 2.0f * m3 * s1.w + 3.0f * m3 * m3;
            ((float4*)g_Bp)[q] = tt;
        }
    } else {
        float local = 0.0f;
        #pragma unroll
        for (int oy = 0; oy < 4; ++oy) {
            int oyg = by * 64 + rbase + oy;
            int q   = ((size_t)b * PLANE + (size_t)oyg * HW + ox) >> 2;
            float4 sg;
            sg.x = sqrtf(fmaxf(acc[oy][0].x + acc[oy][0].y, 0.0f));
            sg.y = sqrtf(fmaxf(acc[oy][1].x + acc[oy][1].y, 0.0f));
            sg.z = sqrtf(fmaxf(acc[oy][2].x + acc[oy][2].y, 0.0f));
            sg.w = sqrtf(fmaxf(acc[oy][3].x + acc[oy][3].y, 0.0f));
            ((float4*)g_A)[q] = sg;
            local += sg.x + sg.y + sg.z + sg.w;
        }
        #pragma unroll
        for (int o = 16; o; o >>= 1) local += __shfl_xor_sync(0xffffffffu, local, o);
        if ((tid & 31) == 0) wsum[tid >> 5] = local;
        __syncthreads();
        if (tid == 0) {
            float s = 0.0f;
            #pragma unroll
            for (int k = 0; k < 8; ++k) s += wsum[k];
            g_part[b * 64 + by * 8 + bx] = s;
        }
    }
}

// ---------------------------------------------------------------------------
// K3: deterministic reduce of 64 block partials per batch -> mean(sigma)
// ---------------------------------------------------------------------------
__global__ void k_mean() {
    __shared__ float ws[2];
    int b = blockIdx.x;
    float v = g_part[b * 64 + threadIdx.x];
    #pragma unroll
    for (int o = 16; o; o >>= 1) v += __shfl_xor_sync(0xffffffffu, v, o);
    if ((threadIdx.x & 31) == 0) ws[threadIdx.x >> 5] = v;
    __syncthreads();
    if (threadIdx.x == 0)
        g_sum[b] = (ws[0] + ws[1]) * (1.0f / (float)PLANE);
}

// ---------------------------------------------------------------------------
// K4: out = (x - m) / max(mean_b, sigma)
// ---------------------------------------------------------------------------
__global__ void k_final(const float* __restrict__ x, float* __restrict__ out) {
    int i = blockIdx.x * blockDim.x + threadIdx.x;   // pixel-quad index
    int b = i >> 16;                                  // 65536 quads per batch
    float mean = g_sum[b];

    float4 m  = ((const float4*)g_M)[i];
    float4 sg = ((const float4*)g_A)[i];
    float r0 = 1.0f / fmaxf(mean, sg.x);
    float r1 = 1.0f / fmaxf(mean, sg.y);
    float r2 = 1.0f / fmaxf(mean, sg.z);
    float r3 = 1.0f / fmaxf(mean, sg.w);

    const float4* xp = (const float4*)x;
    float4 a = xp[i * 3 + 0];
    float4 bb = xp[i * 3 + 1];
    float4 c = xp[i * 3 + 2];

    float4 o0, o1, o2;
    o0.x = (a.x  - m.x) * r0;  o0.y = (a.y  - m.x) * r0;  o0.z = (a.z  - m.x) * r0;
    o0.w = (a.w  - m.y) * r1;
    o1.x = (bb.x - m.y) * r1;  o1.y = (bb.y - m.y) * r1;
    o1.z = (bb.z - m.z) * r2;  o1.w = (bb.w - m.z) * r2;
    o2.x = (c.x  - m.z) * r2;
    o2.y = (c.y  - m.w) * r3;  o2.z = (c.z  - m.w) * r3;  o2.w = (c.w  - m.w) * r3;

    float4* op = (float4*)out;
    op[i * 3 + 0] = o0;
    op[i * 3 + 1] = o1;
    op[i * 3 + 2] = o2;
}

// ---------------------------------------------------------------------------
extern "C" void kernel_launch(void* const* d_in, const int* in_sizes, int n_in,
                              void* d_out, int out_size) {
    const float* x    = (const float*)d_in[0];
    const float* filt = (const float*)d_in[1];
    float* out        = (float*)d_out;

    k_filt<<<1, 128>>>(filt);
    dim3 cgrid(8, 8, NB);
    k_conv<0><<<cgrid, 256>>>(x);
    k_conv<1><<<cgrid, 256>>>(x);
    k_mean<<<NB, 64>>>();
    k_final<<<GROUPS / 256, 256>>>(x, out);
}

// round 5
// speedup vs baseline: 1.0477x; 1.0004x over previous
#include <cuda_runtime.h>

#define HW     512
#define NB     16
#define PLANE  (HW * HW)          // 262144
#define NPIX   (NB * PLANE)       // 4194304
#define GROUPS (NPIX / 4)         // 1048576 pixel-quads

// Scratch planes:
//   g_A : sigma (written by conv1)
//   g_Bp: t = sum_c v^2 (written by conv0, read by conv1)
//   g_M : local mean m
__device__ float  g_A[NPIX];
__device__ float  g_Bp[NPIX];
__device__ float  g_M[NPIX];
__device__ float2 g_fpack[90];        // 9 rows x 10 packed filter pairs
__device__ float  g_part[NB * 64];    // per-block sigma partial sums (8x8 blocks/batch)
__device__ float  g_sum[NB];          // per-batch mean(sigma)

// packed fp32x2 FMA: d += a * b (two independent lanes)
__device__ __forceinline__ void ffma2(float2 &d, const float2 a, const float2 b) {
    asm("fma.rn.f32x2 %0, %1, %2, %0;"
        : "+l"(reinterpret_cast<unsigned long long &>(d))
        : "l"(reinterpret_cast<const unsigned long long &>(a)),
          "l"(reinterpret_cast<const unsigned long long &>(b)));
}

// ---------------------------------------------------------------------------
// K0: normalize filter f = (filt+10)/sum, build packed-pair layout:
//  row t, slots 0..4 : (f[2k], f[2k+1])  with f[9]=0
//  slots 5..8        : (f[2k+1], f[2k+2])
//  slot 9            : (0, f[0])
// ---------------------------------------------------------------------------
__global__ void k_filt(const float* __restrict__ filt) {
    __shared__ float nf[81];
    __shared__ float red[4];
    int t = threadIdx.x;                       // 128 threads
    float v = (t < 81) ? (filt[t] + 10.0f) : 0.0f;
    float s = v;
    #pragma unroll
    for (int o = 16; o; o >>= 1) s += __shfl_xor_sync(0xffffffffu, s, o);
    if ((t & 31) == 0) red[t >> 5] = s;
    __syncthreads();
    float total = red[0] + red[1] + red[2] + red[3];
    if (t < 81) nf[t] = v / total;
    __syncthreads();
    if (t < 90) {
        int r = t / 10, k = t - r * 10;
        const float* f = &nf[r * 9];
        float2 o;
        if (k < 5)      o = make_float2(f[2 * k], (2 * k + 1 < 9) ? f[2 * k + 1] : 0.0f);
        else if (k < 9) { int j = k - 5; o = make_float2(f[2 * j + 1], f[2 * j + 2]); }
        else            o = make_float2(0.0f, f[0]);
        g_fpack[r * 10 + k] = o;
    }
}

// ---------------------------------------------------------------------------
// Conv core: 64x64 output tile per block, 256 threads, 4x4 outputs/thread.
// Smem tile 72 rows x 72 cols (stride 76). Filter-pair packing + FFMA2.
// PHASE 0: loads x (NHWC, C=3), builds S1 tile + center S2 tile.
//          conv(S1) -> m ; t = S2 - 2 m S1 + 3 m^2 -> g_Bp ; m -> g_M
// PHASE 1: loads t plane; conv(t) -> sigma -> g_A ; block partial sums.
// ---------------------------------------------------------------------------
template <int PHASE>
__global__ void __launch_bounds__(256) k_conv(const float* __restrict__ x) {
    __shared__ float  tile[72 * 76];
    __shared__ float  s2c[(PHASE == 0) ? 64 * 64 : 1];
    __shared__ float2 sfp[90];
    __shared__ float  wsum[8];

    const int b  = blockIdx.z;
    const int bx = blockIdx.x;     // 0..7
    const int by = blockIdx.y;     // 0..7
    const int x0 = bx * 64 - 4;
    const int y0 = by * 64 - 4;
    const int tid = threadIdx.x;

    if (tid < 90) sfp[tid] = g_fpack[tid];

    // ---- load tile: 72 rows x 18 quads ----
    if (PHASE == 0) {
        for (int i = tid; i < 72 * 18; i += 256) {
            int row = i / 18, q = i - row * 18;
            int gy = y0 + row, gx = x0 + q * 4;
            float4 a = make_float4(0.f,0.f,0.f,0.f), bb = a, c = a;
            if ((unsigned)gy < (unsigned)HW && (unsigned)gx < (unsigned)HW) {
                const float4* p = (const float4*)x +
                    (((size_t)b * PLANE + (size_t)gy * HW + gx) >> 2) * 3;
                a = p[0]; bb = p[1]; c = p[2];
            }
            float4 s1, s2;
            s1.x = a.x + a.y + a.z;   s2.x = a.x*a.x + a.y*a.y + a.z*a.z;
            s1.y = a.w + bb.x + bb.y; s2.y = a.w*a.w + bb.x*bb.x + bb.y*bb.y;
            s1.z = bb.z + bb.w + c.x; s2.z = bb.z*bb.z + bb.w*bb.w + c.x*c.x;
            s1.w = c.y + c.z + c.w;   s2.w = c.y*c.y + c.z*c.z + c.w*c.w;
            *(float4*)&tile[row * 76 + q * 4] = s1;
            if (row >= 4 && row < 68 && q >= 1 && q <= 16)
                *(float4*)&s2c[(row - 4) * 64 + (q - 1) * 4] = s2;
        }
    } else {
        for (int i = tid; i < 72 * 18; i += 256) {
            int row = i / 18, q = i - row * 18;
            int gy = y0 + row, gx = x0 + q * 4;
            float4 v = make_float4(0.f,0.f,0.f,0.f);
            if ((unsigned)gy < (unsigned)HW && (unsigned)gx < (unsigned)HW)
                v = *(const float4*)&g_Bp[(size_t)b * PLANE + (size_t)gy * HW + gx];
            *(float4*)&tile[row * 76 + q * 4] = v;
        }
    }
    __syncthreads();

    const int tx = tid & 15;       // x quad  -> outputs 4*tx .. 4*tx+3
    const int ty = tid >> 4;       // y quad  -> outputs 4*ty .. 4*ty+3
    const int rbase = ty * 4;

    float2 acc[4][4];
    #pragma unroll
    for (int i = 0; i < 4; ++i)
        #pragma unroll
        for (int j = 0; j < 4; ++j) acc[i][j] = make_float2(0.f, 0.f);

    float2 W[4][6];
    #pragma unroll
    for (int j = 0; j < 4; ++j) {
        const float* p = &tile[(rbase + j) * 76 + tx * 4];
        float4 a = *(const float4*)p, bb = *(const float4*)(p + 4), c = *(const float4*)(p + 8);
        W[j][0] = make_float2(a.x, a.y);  W[j][1] = make_float2(a.z, a.w);
        W[j][2] = make_float2(bb.x, bb.y); W[j][3] = make_float2(bb.z, bb.w);
        W[j][4] = make_float2(c.x, c.y);  W[j][5] = make_float2(c.z, c.w);
    }

    #pragma unroll
    for (int t = 0; t < 9; ++t) {
        const float2* fp = &sfp[t * 10];
        float2 fe0 = fp[0], fe1 = fp[1], fe2 = fp[2], fe3 = fp[3], fe4 = fp[4];
        float2 fo0 = fp[5], fo1 = fp[6], fo2 = fp[7], fo3 = fp[8], f0z = fp[9];
        #pragma unroll
        for (int oy = 0; oy < 4; ++oy) {
            float2* w = W[(t + oy) & 3];
            ffma2(acc[oy][0], fe0, w[0]); ffma2(acc[oy][0], fe1, w[1]);
            ffma2(acc[oy][0], fe2, w[2]); ffma2(acc[oy][0], fe3, w[3]);
            ffma2(acc[oy][0], fe4, w[4]);
            ffma2(acc[oy][2], fe0, w[1]); ffma2(acc[oy][2], fe1, w[2]);
            ffma2(acc[oy][2], fe2, w[3]); ffma2(acc[oy][2], fe3, w[4]);
            ffma2(acc[oy][2], fe4, w[5]);
            ffma2(acc[oy][1], f0z, w[0]); ffma2(acc[oy][1], fo0, w[1]);
            ffma2(acc[oy][1], fo1, w[2]); ffma2(acc[oy][1], fo2, w[3]);
            ffma2(acc[oy][1], fo3, w[4]);
            ffma2(acc[oy][3], f0z, w[1]); ffma2(acc[oy][3], fo0, w[2]);
            ffma2(acc[oy][3], fo1, w[3]); ffma2(acc[oy][3], fo2, w[4]);
            ffma2(acc[oy][3], fo3, w[5]);
        }
        if (t < 8) {
            const float* p = &tile[(rbase + t + 4) * 76 + tx * 4];
            float4 a = *(const float4*)p, bb = *(const float4*)(p + 4), c = *(const float4*)(p + 8);
            float2* w = W[t & 3];
            w[0] = make_float2(a.x, a.y);  w[1] = make_float2(a.z, a.w);
            w[2] = make_float2(bb.x, bb.y); w[3] = make_float2(bb.z, bb.w);
            w[4] = make_float2(c.x, c.y);  w[5] = make_float2(c.z, c.w);
        }
    }

    const int ox  = bx * 64 + tx * 4;

    if (PHASE == 0) {
        #pragma unroll
        for (int oy = 0; oy < 4; ++oy) {
            int oyg = by * 64 + rbase + oy;
            int q   = ((size_t)b * PLANE + (size_t)oyg * HW + ox) >> 2;
            float m0 = acc[oy][0].x + acc[oy][0].y;
            float m1 = acc[oy][1].x + acc[oy][1].y;
            float m2 = acc[oy][2].x + acc[oy][2].y;
            float m3 = acc[oy][3].x + acc[oy][3].y;
            ((float4*)g_M)[q] = make_float4(m0, m1, m2, m3);
            float4 s1 = *(const float4*)&tile[(rbase + oy + 4) * 76 + tx * 4 + 4];
            float4 s2 = *(const float4*)&s2c[(rbase + oy) * 64 + tx * 4];
            float4 tt;
            tt.x = s2.x - 2.0f * m0 * s1.x + 3.0f * m0 * m0;
            tt.y = s2.y - 2.0f * m1 * s1.y + 3.0f * m1 * m1;
            tt.z = s2.z - 2.0f * m2 * s1.z + 3.0f * m2 * m2;
            tt.w = s2.w - 2.0f * m3 * s1.w + 3.0f * m3 * m3;
            ((float4*)g_Bp)[q] = tt;
        }
    } else {
        float local = 0.0f;
        #pragma unroll
        for (int oy = 0; oy < 4; ++oy) {
            int oyg = by * 64 + rbase + oy;
            int q   = ((size_t)b * PLANE + (size_t)oyg * HW + ox) >> 2;
            float4 sg;
            sg.x = sqrtf(fmaxf(acc[oy][0].x + acc[oy][0].y, 0.0f));
            sg.y = sqrtf(fmaxf(acc[oy][1].x + acc[oy][1].y, 0.0f));
            sg.z = sqrtf(fmaxf(acc[oy][2].x + acc[oy][2].y, 0.0f));
            sg.w = sqrtf(fmaxf(acc[oy][3].x + acc[oy][3].y, 0.0f));
            ((float4*)g_A)[q] = sg;
            local += sg.x + sg.y + sg.z + sg.w;
        }
        #pragma unroll
        for (int o = 16; o; o >>= 1) local += __shfl_xor_sync(0xffffffffu, local, o);
        if ((tid & 31) == 0) wsum[tid >> 5] = local;
        __syncthreads();
        if (tid == 0) {
            float s = 0.0f;
            #pragma unroll
            for (int k = 0; k < 8; ++k) s += wsum[k];
            g_part[b * 64 + by * 8 + bx] = s;
        }
    }
}

// ---------------------------------------------------------------------------
// K3: deterministic reduce of 64 block partials per batch -> mean(sigma)
// ---------------------------------------------------------------------------
__global__ void k_mean() {
    __shared__ float ws[2];
    int b = blockIdx.x;
    float v = g_part[b * 64 + threadIdx.x];
    #pragma unroll
    for (int o = 16; o; o >>= 1) v += __shfl_xor_sync(0xffffffffu, v, o);
    if ((threadIdx.x & 31) == 0) ws[threadIdx.x >> 5] = v;
    __syncthreads();
    if (threadIdx.x == 0)
        g_sum[b] = (ws[0] + ws[1]) * (1.0f / (float)PLANE);
}

// ---------------------------------------------------------------------------
// K4: out = (x - m) / max(mean_b, sigma)
// ---------------------------------------------------------------------------
__global__ void k_final(const float* __restrict__ x, float* __restrict__ out) {
    int i = blockIdx.x * blockDim.x + threadIdx.x;   // pixel-quad index
    int b = i >> 16;                                  // 65536 quads per batch
    float mean = g_sum[b];

    float4 m  = ((const float4*)g_M)[i];
    float4 sg = ((const float4*)g_A)[i];
    float r0 = 1.0f / fmaxf(mean, sg.x);
    float r1 = 1.0f / fmaxf(mean, sg.y);
    float r2 = 1.0f / fmaxf(mean, sg.z);
    float r3 = 1.0f / fmaxf(mean, sg.w);

    const float4* xp = (const float4*)x;
    float4 a = xp[i * 3 + 0];
    float4 bb = xp[i * 3 + 1];
    float4 c = xp[i * 3 + 2];

    float4 o0, o1, o2;
    o0.x = (a.x  - m.x) * r0;  o0.y = (a.y  - m.x) * r0;  o0.z = (a.z  - m.x) * r0;
    o0.w = (a.w  - m.y) * r1;
    o1.x = (bb.x - m.y) * r1;  o1.y = (bb.y - m.y) * r1;
    o1.z = (bb.z - m.z) * r2;  o1.w = (bb.w - m.z) * r2;
    o2.x = (c.x  - m.z) * r2;
    o2.y = (c.y  - m.w) * r3;  o2.z = (c.z  - m.w) * r3;  o2.w = (c.w  - m.w) * r3;

    float4* op = (float4*)out;
    op[i * 3 + 0] = o0;
    op[i * 3 + 1] = o1;
    op[i * 3 + 2] = o2;
}

// ---------------------------------------------------------------------------
extern "C" void kernel_launch(void* const* d_in, const int* in_sizes, int n_in,
                              void* d_out, int out_size) {
    const float* x    = (const float*)d_in[0];
    const float* filt = (const float*)d_in[1];
    float* out        = (float*)d_out;

    k_filt<<<1, 128>>>(filt);
    dim3 cgrid(8, 8, NB);
    k_conv<0><<<cgrid, 256>>>(x);
    k_conv<1><<<cgrid, 256>>>(x);
    k_mean<<<NB, 64>>>();
    k_final<<<GROUPS / 256, 256>>>(x, out);
}